// round 1
// baseline (speedup 1.0000x reference)
#include <cuda_runtime.h>
#include <cuda_bf16.h>

// DeformConv 1-channel, K=3, B=8, H=W=512, fp32.
// Strategy: HBM-bound on the 151MB offset tensor. Stage the input tile
// (zero-padded halo) in shared memory so the 36 bilinear corner reads per
// pixel are conflict-free LDS instead of global gathers. One pixel per
// thread keeps lane->smem addresses stride-1 (no bank conflicts).

static constexpr int BB = 8;
static constexpr int HH = 512;
static constexpr int WW = 512;

static constexpr int TW = 32;          // output tile width  (== blockDim.x)
static constexpr int TH = 16;          // output tile height (== blockDim.y)
static constexpr int TILE_W = TW + 3;  // 35: cols [c0-1, c0+TW+1]
static constexpr int TILE_H = TH + 3;  // 19: rows [r0-1, r0+TH+1]
static constexpr int PITCH  = 36;      // row pitch (words); stride-1 lanes -> conflict-free

__global__ __launch_bounds__(TW * TH)
void deform_conv_kernel(const float* __restrict__ inp,
                        const float* __restrict__ weight,
                        const float* __restrict__ off,
                        float* __restrict__ out)
{
    __shared__ float tile[TILE_H * PITCH];

    const int b  = blockIdx.z;
    const int r0 = blockIdx.y * TH;
    const int c0 = blockIdx.x * TW;

    const float* img = inp + (size_t)b * (HH * WW);

    // ---- cooperative zero-padded tile fill ----
    const int tid = threadIdx.y * TW + threadIdx.x;
    #pragma unroll
    for (int i = tid; i < TILE_H * TILE_W; i += TW * TH) {
        int ty = i / TILE_W;
        int tx = i - ty * TILE_W;
        int gy = r0 - 1 + ty;
        int gx = c0 - 1 + tx;
        float v = 0.0f;
        if (gy >= 0 && gy < HH && gx >= 0 && gx < WW)
            v = __ldg(img + gy * WW + gx);
        tile[ty * PITCH + tx] = v;
    }

    // weights: 9 uniform-address loads (single L1 wavefront each)
    float wk[9];
    #pragma unroll
    for (int k = 0; k < 9; k++) wk[k] = __ldg(weight + k);

    __syncthreads();

    const int gh = r0 + threadIdx.y;
    const int gw = c0 + threadIdx.x;

    // offset layout: (B, 18, H, W); channel 2k = oy, 2k+1 = ox for tap k
    const float* offp = off + (size_t)b * 18 * HH * WW + (size_t)gh * WW + gw;
    const int cs = HH * WW;

    // prefetch all 18 offsets up front (max MLP against DRAM latency)
    float oy[9], ox[9];
    #pragma unroll
    for (int k = 0; k < 9; k++) {
        oy[k] = __ldg(offp + (2 * k)     * cs);
        ox[k] = __ldg(offp + (2 * k + 1) * cs);
    }

    float acc = 0.0f;
    #pragma unroll
    for (int k = 0; k < 9; k++) {
        const int ky = k / 3 - 1;
        const int kx = k % 3 - 1;

        float y = (float)(gh + ky) + oy[k];
        float x = (float)(gw + kx) + ox[k];

        float y0f = floorf(y);
        float x0f = floorf(x);
        float ly = y - y0f;
        float lx = x - x0f;
        float hy = 1.0f - ly;
        float hx = 1.0f - lx;

        int iy0 = (int)y0f;
        int ix0 = (int)x0f;

        int ty = iy0 - (r0 - 1);
        int tx = ix0 - (c0 - 1);

        float v00, v01, v10, v11;
        if (ty >= 0 && (ty + 1) < TILE_H && tx >= 0 && (tx + 1) < TILE_W) {
            // fast path: all four corners inside the staged (zero-padded) tile.
            // Zero padding == reference's per-corner validity mask.
            const float* t = tile + ty * PITCH + tx;
            v00 = t[0];
            v01 = t[1];
            v10 = t[PITCH];
            v11 = t[PITCH + 1];
        } else {
            // general fallback (never taken for offsets in [0,1)): global reads
            // with per-corner validity, exactly matching the reference rule.
            int iy1 = iy0 + 1, ix1 = ix0 + 1;
            v00 = (iy0 >= 0 && iy0 < HH && ix0 >= 0 && ix0 < WW) ? __ldg(img + iy0 * WW + ix0) : 0.0f;
            v01 = (iy0 >= 0 && iy0 < HH && ix1 >= 0 && ix1 < WW) ? __ldg(img + iy0 * WW + ix1) : 0.0f;
            v10 = (iy1 >= 0 && iy1 < HH && ix0 >= 0 && ix0 < WW) ? __ldg(img + iy1 * WW + ix0) : 0.0f;
            v11 = (iy1 >= 0 && iy1 < HH && ix1 >= 0 && ix1 < WW) ? __ldg(img + iy1 * WW + ix1) : 0.0f;
        }

        float val = fmaf(hy, fmaf(hx, v00, lx * v01),
                         ly * fmaf(hx, v10, lx * v11));
        acc = fmaf(wk[k], val, acc);
    }

    out[(size_t)b * HH * WW + (size_t)gh * WW + gw] = acc;
}

extern "C" void kernel_launch(void* const* d_in, const int* in_sizes, int n_in,
                              void* d_out, int out_size)
{
    const float* inp    = (const float*)d_in[0];  // (8, 512, 512)
    const float* weight = (const float*)d_in[1];  // (1, 1, 3, 3)
    const float* off    = (const float*)d_in[2];  // (8, 18, 512, 512)
    float* out = (float*)d_out;                   // (8, 512, 512)

    dim3 block(TW, TH);                 // 512 threads
    dim3 grid(WW / TW, HH / TH, BB);    // (16, 32, 8)
    deform_conv_kernel<<<grid, block>>>(inp, weight, off, out);
}

// round 2
// speedup vs baseline: 1.4207x; 1.4207x over previous
#include <cuda_runtime.h>
#include <cuda_bf16.h>

// DeformConv 1-ch, K=3, B=8, H=W=512, fp32.
// R2 design: latency-bound fix.
//  - 2 px/thread (consecutive x) -> offset loads are LDG.64, output STG.64.
//  - pair-duplicated smem tile (float2 entries): each bilinear tap = 2x LDS.64.
//  - __ldcs for the streamed offset tensor (151MB, zero reuse).

static constexpr int BB = 8;
static constexpr int HH = 512;
static constexpr int WW = 512;

static constexpr int BX = 32;          // threads x
static constexpr int BY = 8;           // threads y
static constexpr int OW = 64;          // output tile width  (2 px per thread)
static constexpr int OH = 8;           // output tile height
static constexpr int TILE_H = OH + 3;  // 11 rows  [r0-1 .. r0+9]
static constexpr int TILE_W = OW + 3;  // 67 pair-entries [c0-1 .. c0+65]
static constexpr int PITCH  = 68;      // entry pitch

__global__ __launch_bounds__(BX * BY)
void deform_conv_kernel(const float* __restrict__ inp,
                        const float* __restrict__ weight,
                        const float* __restrict__ off,
                        float* __restrict__ out)
{
    // entry e holds (v[e], v[e+1]) so one LDS.64 fetches a horizontal corner pair
    __shared__ float2 tile[TILE_H * PITCH];

    const int b  = blockIdx.z;
    const int r0 = blockIdx.y * OH;
    const int c0 = blockIdx.x * OW;

    const float* img = inp + (size_t)b * (HH * WW);
    const int tid = threadIdx.y * BX + threadIdx.x;

    // ---- cooperative zero-padded pair-tile fill ----
    #pragma unroll
    for (int i = tid; i < TILE_H * TILE_W; i += BX * BY) {
        int ty = i / TILE_W;
        int tx = i - ty * TILE_W;
        int gy = r0 - 1 + ty;
        int gx = c0 - 1 + tx;
        float v0 = 0.0f, v1 = 0.0f;
        if (gy >= 0 && gy < HH) {
            const float* row = img + gy * WW;
            if (gx >= 0 && gx < WW)         v0 = __ldg(row + gx);
            if (gx + 1 >= 0 && gx + 1 < WW) v1 = __ldg(row + gx + 1);
        }
        tile[ty * PITCH + tx] = make_float2(v0, v1);
    }

    float wk[9];
    #pragma unroll
    for (int k = 0; k < 9; k++) wk[k] = __ldg(weight + k);

    const int gh  = r0 + threadIdx.y;
    const int gwb = c0 + 2 * threadIdx.x;      // 8B-aligned pixel pair
    const int cs  = HH * WW;

    // prefetch all 18 offset channels as float2 (streaming: no reuse)
    const float* offp = off + (size_t)b * 18 * cs + (size_t)gh * WW + gwb;
    float2 o[18];
    #pragma unroll
    for (int ch = 0; ch < 18; ch++)
        o[ch] = __ldcs((const float2*)(offp + (size_t)ch * cs));

    __syncthreads();

    float acc0 = 0.0f, acc1 = 0.0f;

    #pragma unroll
    for (int k = 0; k < 9; k++) {
        const int ky = k / 3 - 1;
        const int kx = k % 3 - 1;
        const float2 oy = o[2 * k];
        const float2 ox = o[2 * k + 1];

        #pragma unroll
        for (int j = 0; j < 2; j++) {
            float y = (float)(gh + ky) + (j ? oy.y : oy.x);
            float x = (float)(gwb + j + kx) + (j ? ox.y : ox.x);

            int iy0 = __float2int_rd(y);
            int ix0 = __float2int_rd(x);
            float ly = y - (float)iy0;
            float lx = x - (float)ix0;
            float hy = 1.0f - ly;
            float hx = 1.0f - lx;

            int ty = iy0 - (r0 - 1);
            int tx = ix0 - (c0 - 1);

            float v00, v01, v10, v11;
            if ((unsigned)ty < (unsigned)(TILE_H - 1) &&
                (unsigned)tx < (unsigned)(TILE_W - 1)) {
                // fast path: two LDS.64 (always taken for offsets in [0,1))
                const float2* t = tile + ty * PITCH + tx;
                float2 top = t[0];
                float2 bot = t[PITCH];
                v00 = top.x; v01 = top.y; v10 = bot.x; v11 = bot.y;
            } else {
                // general fallback, exact per-corner validity like the reference
                int iy1 = iy0 + 1, ix1 = ix0 + 1;
                v00 = (iy0 >= 0 && iy0 < HH && ix0 >= 0 && ix0 < WW) ? __ldg(img + iy0 * WW + ix0) : 0.0f;
                v01 = (iy0 >= 0 && iy0 < HH && ix1 >= 0 && ix1 < WW) ? __ldg(img + iy0 * WW + ix1) : 0.0f;
                v10 = (iy1 >= 0 && iy1 < HH && ix0 >= 0 && ix0 < WW) ? __ldg(img + iy1 * WW + ix0) : 0.0f;
                v11 = (iy1 >= 0 && iy1 < HH && ix1 >= 0 && ix1 < WW) ? __ldg(img + iy1 * WW + ix1) : 0.0f;
            }

            float val = fmaf(hy, fmaf(hx, v00, lx * v01),
                             ly * fmaf(hx, v10, lx * v11));
            if (j == 0) acc0 = fmaf(wk[k], val, acc0);
            else        acc1 = fmaf(wk[k], val, acc1);
        }
    }

    float2* op = (float2*)(out + (size_t)b * cs + (size_t)gh * WW + gwb);
    *op = make_float2(acc0, acc1);
}

extern "C" void kernel_launch(void* const* d_in, const int* in_sizes, int n_in,
                              void* d_out, int out_size)
{
    const float* inp    = (const float*)d_in[0];  // (8, 512, 512)
    const float* weight = (const float*)d_in[1];  // (1, 1, 3, 3)
    const float* off    = (const float*)d_in[2];  // (8, 18, 512, 512)
    float* out = (float*)d_out;                   // (8, 512, 512)

    dim3 block(BX, BY);                       // 256 threads
    dim3 grid(WW / OW, HH / OH, BB);          // (8, 64, 8)
    deform_conv_kernel<<<grid, block>>>(inp, weight, off, out);
}